// round 17
// baseline (speedup 1.0000x reference)
#include <cuda_runtime.h>
#include <cuda_fp16.h>
#include <cstdint>
#include <math.h>

// ---------------------------------------------------------------------------
// Self-attention B=4, S=2048, D=1024 — Round 16 (resubmit of the proven
// 872.5us R14 kernel after infra failure; no code changes).
//   - fp16 split GEMMs (mma.sync.m16n8k16), 128x64 block, 64x32 warp tiles,
//     BKE=32, 2-stage cp.async, 3 CTAs/SM (full) / 4 CTAs/SM (1-term P@V).
//   - merged QKV projection launch (gridDim.z=3), V lo-store skipped.
//   - float4 + warp-shuffle softmax, single-fp16 P.
// Precision (calibrated): Q,K,scores 3-term; P@V 1-term. rel_err ~2.66e-4.
// ---------------------------------------------------------------------------

#define BATCH 4
#define SEQ   2048
#define DIM   1024

typedef __half f16;

#define M1 (BATCH * SEQ)            // 8192
#define PSL ((long)M1 * DIM)

// ---------------- scratch ---------------------------------------------------
__device__ f16   g_ah[PSL], g_al[PSL];
__device__ f16   g_wth[3 * DIM * DIM], g_wtl[3 * DIM * DIM];
__device__ f16   g_qkvh[3 * PSL], g_qkvl[3 * PSL];
__device__ f16   g_vth[BATCH * DIM * SEQ];
__device__ float g_s [BATCH * SEQ * SEQ];
__device__ f16   g_ph[BATCH * SEQ * SEQ];

// ---------------- helpers ---------------------------------------------------
__device__ __forceinline__ uint32_t smem_u32(const void* p) {
    uint32_t a;
    asm("{ .reg .u64 t; cvta.to.shared.u64 t, %1; cvt.u32.u64 %0, t; }"
        : "=r"(a) : "l"(p));
    return a;
}
__device__ __forceinline__ void cp16(uint32_t dst, const void* src) {
    asm volatile("cp.async.cg.shared.global [%0], [%1], 16;"
                 :: "r"(dst), "l"(src));
}
#define CP_COMMIT() asm volatile("cp.async.commit_group;" ::: "memory")
#define CP_WAIT(n)  asm volatile("cp.async.wait_group %0;" :: "n"(n) : "memory")

__device__ __forceinline__ void ldm_x4(uint32_t* r, uint32_t addr) {
    asm volatile("ldmatrix.sync.aligned.m8n8.x4.shared.b16 {%0,%1,%2,%3}, [%4];"
                 : "=r"(r[0]), "=r"(r[1]), "=r"(r[2]), "=r"(r[3]) : "r"(addr));
}
__device__ __forceinline__ void mma_f16(float* c, const uint32_t* a,
                                        const uint32_t* b) {
    asm volatile(
        "mma.sync.aligned.m16n8k16.row.col.f32.f16.f16.f32 "
        "{%0,%1,%2,%3}, {%4,%5,%6,%7}, {%8,%9}, {%0,%1,%2,%3};"
        : "+f"(c[0]), "+f"(c[1]), "+f"(c[2]), "+f"(c[3])
        : "r"(a[0]), "r"(a[1]), "r"(a[2]), "r"(a[3]), "r"(b[0]), "r"(b[1]));
}
__device__ __forceinline__ uint32_t hpack(f16 a, f16 b) {
    union { __half2 v; uint32_t u; } t;
    t.v = __halves2half2(a, b);
    return t.u;
}
__device__ __forceinline__ void split2(float x, float y, uint32_t& hi,
                                       uint32_t& lo) {
    f16 hx = __float2half_rn(x), hy = __float2half_rn(y);
    hi = hpack(hx, hy);
    lo = hpack(__float2half_rn(x - __half2float(hx)),
               __float2half_rn(y - __half2float(hy)));
}

// ---------------- GEMM config ----------------------------------------------
#define BM 128
#define BN 64
#define BKE 32                 // fp16 elems per stage (2 x k16)
#define GTHREADS 128           // 4 warps: 2(M) x 2(N), warp tile 64x32

#define ROWB   80              // 64B data + 16B pad
#define AT_B   (128 * ROWB)    // 10240
#define BT_B   (64 * ROWB)     // 5120

#define OUT_F32   0
#define OUT_SPLIT 1

// host-side smem sizes (mirror kernel constexpr)
#define SMEM_FULL (2 * (2 * AT_B + 2 * BT_B))   // 61440: 3 CTAs/SM
#define SMEM_PV   (2 * (AT_B + BT_B))           // 30720: 4 CTAs/SM

template<int R>
__device__ __forceinline__ void issue_tile(const f16* src, uint32_t dst,
                                           int K, long k0, int tid) {
#pragma unroll
    for (int it = 0; it < R * 4 / GTHREADS; it++) {
        int c = tid + it * GTHREADS;
        int row = c >> 2, col = c & 3;
        cp16(dst + row * ROWB + col * 16, src + (long)row * K + k0 + col * 8);
    }
}

// NT GEMM: C[m][n] = sum_k A[m][k]*B[n][k].
// Terms: hi*hi (+ hi*lo if B_SPLIT) (+ lo*hi if A_SPLIT).
template<int OUT_MODE, bool A_SPLIT, bool B_SPLIT, bool QKV_BIAS, int MINB>
__global__ void __launch_bounds__(GTHREADS, MINB)
f16_gemm(const f16* __restrict__ Ah, const f16* __restrict__ Al,
         const f16* __restrict__ Bh, const f16* __restrict__ Bl,
         const float* __restrict__ bias0, const float* __restrict__ bias1,
         const float* __restrict__ bias2,
         float* __restrict__ Cf, f16* __restrict__ Ch, f16* __restrict__ Cl,
         int M, int N, int K, long sA, long sB, long sC)
{
    // stage layout depends on which tiles exist
    constexpr uint32_t O_ALO = AT_B;
    constexpr uint32_t O_BHI = AT_B * (A_SPLIT ? 2 : 1);
    constexpr uint32_t O_BLO = O_BHI + BT_B;
    constexpr uint32_t STB   = O_BHI + BT_B * (B_SPLIT ? 2 : 1);

    extern __shared__ char smem[];
    const uint32_t sbase = smem_u32(smem);
    const int tid  = threadIdx.x;
    const int lane = tid & 31;
    const int wid  = tid >> 5;
    const int wm0  = (wid >> 1) * 64;
    const int wn0  = (wid & 1) * 32;
    const int m0 = blockIdx.y * BM;
    const int n0 = blockIdx.x * BN;

    const float* bias = nullptr;
    if (QKV_BIAS)
        bias = (blockIdx.z == 0) ? bias0 : (blockIdx.z == 1) ? bias1 : bias2;

    const f16* Ahb = Ah + (long)blockIdx.z * sA + (long)m0 * K;
    const f16* Alb = A_SPLIT ? (Al + (long)blockIdx.z * sA + (long)m0 * K) : nullptr;
    const f16* Bhb = Bh + (long)blockIdx.z * sB + (long)n0 * K;
    const f16* Blb = B_SPLIT ? (Bl + (long)blockIdx.z * sB + (long)n0 * K) : nullptr;

    const uint32_t partA = (uint32_t)((wm0 + (lane & 15)) * ROWB
                                      + ((lane >> 4) << 4));
    const uint32_t partB = (uint32_t)((wn0 + (lane & 7) + ((lane >> 4) << 3)) * ROWB
                                      + ((lane & 8) ? 16 : 0));

    float acc[4][4][4];
#pragma unroll
    for (int i = 0; i < 4; i++)
#pragma unroll
        for (int j = 0; j < 4; j++)
#pragma unroll
            for (int r = 0; r < 4; r++) acc[i][j][r] = 0.f;

    const int NC = K / BKE;

    issue_tile<128>(Ahb, sbase + 0, K, 0, tid);
    if (A_SPLIT) issue_tile<128>(Alb, sbase + O_ALO, K, 0, tid);
    issue_tile<64> (Bhb, sbase + O_BHI, K, 0, tid);
    if (B_SPLIT) issue_tile<64> (Blb, sbase + O_BLO, K, 0, tid);
    CP_COMMIT();

    for (int i = 0; i < NC; i++) {
        __syncthreads();
        if (i + 1 < NC) {
            uint32_t sb = sbase + (uint32_t)(((i + 1) & 1) * STB);
            long k0 = (long)(i + 1) * BKE;
            issue_tile<128>(Ahb, sb + 0, K, k0, tid);
            if (A_SPLIT) issue_tile<128>(Alb, sb + O_ALO, K, k0, tid);
            issue_tile<64> (Bhb, sb + O_BHI, K, k0, tid);
            if (B_SPLIT) issue_tile<64> (Blb, sb + O_BLO, K, k0, tid);
            CP_COMMIT();
            CP_WAIT(1);
        } else {
            CP_WAIT(0);
        }
        __syncthreads();

        const uint32_t st = sbase + (uint32_t)((i & 1) * STB);
#pragma unroll
        for (int ks = 0; ks < 2; ks++) {
            uint32_t ah[4][4], al[4][4], bh[4][2], bl[4][2];
#pragma unroll
            for (int mf = 0; mf < 4; mf++) {
                uint32_t off = (uint32_t)(mf * 16 * ROWB + ks * 32) + partA;
                ldm_x4(ah[mf], st + 0 + off);
                if (A_SPLIT) ldm_x4(al[mf], st + O_ALO + off);
            }
#pragma unroll
            for (int nf2 = 0; nf2 < 2; nf2++) {
                uint32_t off = (uint32_t)(nf2 * 16 * ROWB + ks * 32) + partB;
                uint32_t t[4];
                ldm_x4(t, st + O_BHI + off);
                bh[nf2 * 2][0] = t[0]; bh[nf2 * 2][1] = t[1];
                bh[nf2 * 2 + 1][0] = t[2]; bh[nf2 * 2 + 1][1] = t[3];
                if (B_SPLIT) {
                    ldm_x4(t, st + O_BLO + off);
                    bl[nf2 * 2][0] = t[0]; bl[nf2 * 2][1] = t[1];
                    bl[nf2 * 2 + 1][0] = t[2]; bl[nf2 * 2 + 1][1] = t[3];
                }
            }
#pragma unroll
            for (int nf = 0; nf < 4; nf++)
#pragma unroll
                for (int mf = 0; mf < 4; mf++) {
                    mma_f16(acc[mf][nf], ah[mf], bh[nf]);
                    if (B_SPLIT) mma_f16(acc[mf][nf], ah[mf], bl[nf]);
                    if (A_SPLIT) mma_f16(acc[mf][nf], al[mf], bh[nf]);
                }
        }
    }

    // epilogue
    const int gid = lane >> 2, tig = lane & 3;
#pragma unroll
    for (int mf = 0; mf < 4; mf++) {
        int r0 = m0 + wm0 + mf * 16 + gid;
#pragma unroll
        for (int nf = 0; nf < 4; nf++) {
            int c0 = n0 + wn0 + nf * 8 + tig * 2;
            float bx = 0.f, by = 0.f;
            if (QKV_BIAS) { bx = bias[c0]; by = bias[c0 + 1]; }
            float x0 = acc[mf][nf][0] + bx, y0 = acc[mf][nf][1] + by;
            float x1 = acc[mf][nf][2] + bx, y1 = acc[mf][nf][3] + by;
            long o0 = (long)(r0) * N + c0 + (long)blockIdx.z * sC;
            long o1 = (long)(r0 + 8) * N + c0 + (long)blockIdx.z * sC;
            if (OUT_MODE == OUT_SPLIT) {
                uint32_t h, l;
                split2(x0, y0, h, l);
                *(uint32_t*)(Ch + o0) = h;
                if (!QKV_BIAS || blockIdx.z < 2) *(uint32_t*)(Cl + o0) = l;
                split2(x1, y1, h, l);
                *(uint32_t*)(Ch + o1) = h;
                if (!QKV_BIAS || blockIdx.z < 2) *(uint32_t*)(Cl + o1) = l;
            } else {
                float* Cb = Cf + (long)blockIdx.z * sC;
                *(float2*)(Cb + (long)r0 * N + c0) = make_float2(x0, y0);
                *(float2*)(Cb + (long)(r0 + 8) * N + c0) = make_float2(x1, y1);
            }
        }
    }
}

// ---------------- split a ---------------------------------------------------
__global__ void __launch_bounds__(256)
split_kernel(const float* __restrict__ src, f16* __restrict__ h,
             f16* __restrict__ l)
{
    long idx = (long)blockIdx.x * 256 + threadIdx.x;
    float2 v = ((const float2*)src)[idx];
    uint32_t hw, lw;
    split2(v.x, v.y, hw, lw);
    ((uint32_t*)h)[idx] = hw;
    ((uint32_t*)l)[idx] = lw;
}

// ---------------- weight transpose + split ----------------------------------
__global__ void __launch_bounds__(256)
wsplit_kernel(const float* __restrict__ w0, const float* __restrict__ w1,
              const float* __restrict__ w2, f16* __restrict__ h,
              f16* __restrict__ l)
{
    __shared__ float t[32][33];
    const float* w = (blockIdx.z == 0) ? w0 : (blockIdx.z == 1) ? w1 : w2;
    h += (long)blockIdx.z * DIM * DIM;
    l += (long)blockIdx.z * DIM * DIM;
    int x = blockIdx.x * 32 + threadIdx.x;
    int y = blockIdx.y * 32 + threadIdx.y;
#pragma unroll
    for (int j = 0; j < 32; j += 8)
        t[threadIdx.y + j][threadIdx.x] = w[(long)(y + j) * DIM + x];
    __syncthreads();
    x = blockIdx.y * 32 + threadIdx.x;
    y = blockIdx.x * 32 + threadIdx.y;
#pragma unroll
    for (int j = 0; j < 32; j += 8) {
        float v = t[threadIdx.x][threadIdx.y + j];
        f16 hv = __float2half_rn(v);
        h[(long)(y + j) * DIM + x] = hv;
        l[(long)(y + j) * DIM + x] =
            __float2half_rn(v - __half2float(hv));
    }
}

// ---------------- f16 transpose ---------------------------------------------
__global__ void __launch_bounds__(256)
transpose_f16(const uint16_t* __restrict__ src, uint16_t* __restrict__ dst,
              int R, int C, long sS, long sD)
{
    __shared__ uint16_t t[32][33];
    src += (long)blockIdx.z * sS;
    dst += (long)blockIdx.z * sD;
    int x = blockIdx.x * 32 + threadIdx.x;
    int y = blockIdx.y * 32 + threadIdx.y;
#pragma unroll
    for (int j = 0; j < 32; j += 8)
        t[threadIdx.y + j][threadIdx.x] = src[(long)(y + j) * C + x];
    __syncthreads();
    x = blockIdx.y * 32 + threadIdx.x;
    y = blockIdx.x * 32 + threadIdx.y;
#pragma unroll
    for (int j = 0; j < 32; j += 8)
        dst[(long)(y + j) * R + x] = t[threadIdx.x][threadIdx.y + j];
}

// ---------------- softmax -> single fp16 P (float4 + shuffle) ---------------
__global__ void __launch_bounds__(256)
softmax_f16(const float* __restrict__ S, f16* __restrict__ Ph)
{
    const float4* row = (const float4*)(S + (long)blockIdx.x * SEQ);
    uint2* oh = (uint2*)(Ph + (long)blockIdx.x * SEQ);
    __shared__ float wmax[8], wsum[8];
    const int tid  = threadIdx.x;
    const int lane = tid & 31;
    const int wrp  = tid >> 5;

    float4 e0 = row[tid], e1 = row[tid + 256];

    // row max
    float m = fmaxf(fmaxf(fmaxf(e0.x, e0.y), fmaxf(e0.z, e0.w)),
                    fmaxf(fmaxf(e1.x, e1.y), fmaxf(e1.z, e1.w)));
#pragma unroll
    for (int o = 16; o > 0; o >>= 1)
        m = fmaxf(m, __shfl_xor_sync(0xFFFFFFFFu, m, o));
    if (lane == 0) wmax[wrp] = m;
    __syncthreads();
    m = wmax[0];
#pragma unroll
    for (int j = 1; j < 8; j++) m = fmaxf(m, wmax[j]);

    // exp + row sum
    e0.x = __expf(e0.x - m); e0.y = __expf(e0.y - m);
    e0.z = __expf(e0.z - m); e0.w = __expf(e0.w - m);
    e1.x = __expf(e1.x - m); e1.y = __expf(e1.y - m);
    e1.z = __expf(e1.z - m); e1.w = __expf(e1.w - m);
    float s = (e0.x + e0.y) + (e0.z + e0.w) + (e1.x + e1.y) + (e1.z + e1.w);
#pragma unroll
    for (int o = 16; o > 0; o >>= 1)
        s += __shfl_xor_sync(0xFFFFFFFFu, s, o);
    if (lane == 0) wsum[wrp] = s;
    __syncthreads();
    s = wsum[0];
#pragma unroll
    for (int j = 1; j < 8; j++) s += wsum[j];
    float inv = 1.f / s;

    uint2 p0, p1;
    p0.x = hpack(__float2half_rn(e0.x * inv), __float2half_rn(e0.y * inv));
    p0.y = hpack(__float2half_rn(e0.z * inv), __float2half_rn(e0.w * inv));
    p1.x = hpack(__float2half_rn(e1.x * inv), __float2half_rn(e1.y * inv));
    p1.y = hpack(__float2half_rn(e1.z * inv), __float2half_rn(e1.w * inv));
    oh[tid] = p0;
    oh[tid + 256] = p1;
}

// ---------------------------------------------------------------------------
extern "C" void kernel_launch(void* const* d_in, const int* in_sizes, int n_in,
                              void* d_out, int out_size)
{
    const float* a   = (const float*)d_in[0];
    const float* w_q = (const float*)d_in[1];
    const float* b_q = (const float*)d_in[2];
    const float* w_k = (const float*)d_in[3];
    const float* b_k = (const float*)d_in[4];
    const float* w_v = (const float*)d_in[5];
    const float* b_v = (const float*)d_in[6];
    float* out = (float*)d_out;

    f16 *ah, *al, *wth, *wtl, *qkvh, *qkvl, *vth, *ph;
    float* s;
    cudaGetSymbolAddress((void**)&ah,   g_ah);   cudaGetSymbolAddress((void**)&al,   g_al);
    cudaGetSymbolAddress((void**)&wth,  g_wth);  cudaGetSymbolAddress((void**)&wtl,  g_wtl);
    cudaGetSymbolAddress((void**)&qkvh, g_qkvh); cudaGetSymbolAddress((void**)&qkvl, g_qkvl);
    cudaGetSymbolAddress((void**)&vth,  g_vth);
    cudaGetSymbolAddress((void**)&ph,   g_ph);
    cudaGetSymbolAddress((void**)&s,    g_s);

    f16 *qh = qkvh,        *ql = qkvl;
    f16 *kh = qkvh + PSL,  *kl = qkvl + PSL;
    f16 *vh = qkvh + 2*PSL;

    cudaFuncSetAttribute(f16_gemm<OUT_SPLIT, true, true, true, 3>,
                         cudaFuncAttributeMaxDynamicSharedMemorySize, SMEM_FULL);
    cudaFuncSetAttribute(f16_gemm<OUT_F32, true, true, false, 3>,
                         cudaFuncAttributeMaxDynamicSharedMemorySize, SMEM_FULL);
    cudaFuncSetAttribute(f16_gemm<OUT_F32, false, false, false, 4>,
                         cudaFuncAttributeMaxDynamicSharedMemorySize, SMEM_PV);

    // 0) operand prep
    split_kernel<<<(long)M1 * DIM / 512, 256>>>(a, ah, al);
    {
        dim3 grid(DIM / 32, DIM / 32, 3);
        dim3 blk(32, 8, 1);
        wsplit_kernel<<<grid, blk>>>(w_q, w_k, w_v, wth, wtl);
    }

    // 1) ALL projections in ONE launch (z=0:Q, 1:K, 2:V)
    {
        dim3 grid(DIM / BN, M1 / BM, 3);
        f16_gemm<OUT_SPLIT, true, true, true, 3><<<grid, GTHREADS, SMEM_FULL>>>(
            ah, al, wth, wtl, b_q, b_k, b_v,
            nullptr, qkvh, qkvl, M1, DIM, DIM,
            0, (long)DIM * DIM, PSL);
    }

    // 2) vt = transpose(vh)
    {
        dim3 grid(DIM / 32, SEQ / 32, BATCH);
        dim3 blk(32, 8, 1);
        transpose_f16<<<grid, blk>>>((const uint16_t*)vh, (uint16_t*)vth,
                                     SEQ, DIM, (long)SEQ * DIM, (long)DIM * SEQ);
    }

    // 3) scores = q @ k^T (fp32 out, 3-term)
    {
        dim3 grid(SEQ / BN, SEQ / BM, BATCH);
        f16_gemm<OUT_F32, true, true, false, 3><<<grid, GTHREADS, SMEM_FULL>>>(
            qh, ql, kh, kl, nullptr, nullptr, nullptr,
            s, nullptr, nullptr,
            SEQ, SEQ, DIM, (long)SEQ * DIM, (long)SEQ * DIM, (long)SEQ * SEQ);
    }

    // 4) softmax -> single fp16 P
    softmax_f16<<<BATCH * SEQ, 256>>>(s, ph);

    // 5) out = P @ vt^T (fp32 out, 1-term, 4 CTAs/SM)
    {
        dim3 grid(DIM / BN, SEQ / BM, BATCH);
        f16_gemm<OUT_F32, false, false, false, 4><<<grid, GTHREADS, SMEM_PV>>>(
            ph, nullptr, vth, nullptr, nullptr, nullptr, nullptr,
            out, nullptr, nullptr,
            SEQ, DIM, SEQ, (long)SEQ * SEQ, (long)DIM * SEQ, (long)SEQ * DIM);
    }
}